// round 1
// baseline (speedup 1.0000x reference)
#include <cuda_runtime.h>
#include <math.h>

#define Bsz   4
#define Lsz   4096
#define Esz   1024
#define Hsz   16
#define Dsz   64
#define HEADS 64
#define SPLIT 8
#define CHUNK 512            // Lsz / SPLIT

#define PART   8320          // A(4096) + B(4096) + ks(64) + kc(64)
#define OFF_A  0
#define OFF_B  4096
#define OFF_KS 8192
#define OFF_KC 8256

// Scratch (no allocations allowed in kernel_launch)
__device__ float g_part[HEADS * SPLIT * PART];   // ~17 MB
__device__ float g_kv[HEADS * PART];             // ~2.1 MB

// ---------------------------------------------------------------------------
// Phase 1: per (head, L-split) partial accumulation of
//   A[d][m] = sum_l s_l * relu(k)[d] * m_l * (v[m] * m_l)
//   B[d][m] = same with cos
//   ks[d]   = sum_l s_l * relu(k)[d] * m_l     (kc with cos)
// ---------------------------------------------------------------------------
__global__ __launch_bounds__(256) void k_phase1(const float* __restrict__ K,
                                                const float* __restrict__ V,
                                                const float* __restrict__ M) {
    int blk = blockIdx.x;
    int n  = blk >> 3;         // head (0..63)
    int sp = blk & 7;          // L split (0..7)
    int b = n >> 4, h = n & 15;
    int l0 = sp * CHUNK;

    const float* kb = K + ((size_t)b * Lsz + l0) * Esz + h * Dsz;
    const float* vb = V + ((size_t)b * Lsz + l0) * Esz + h * Dsz;
    const float* mb = M + (size_t)b * Lsz + l0;

    __shared__ float ksh[512];
    __shared__ float vsh[512];
    __shared__ float ssh[8], csh[8], msh[8];

    int t  = threadIdx.x;
    int dg = t >> 4;           // 0..15 -> d = dg*4..dg*4+3
    int mg = t & 15;           // 0..15 -> m = mg*4..mg*4+3

    float aA[4][4] = {{0.f}};
    float aB[4][4] = {{0.f}};
    float aks[4] = {0.f, 0.f, 0.f, 0.f};
    float akc[4] = {0.f, 0.f, 0.f, 0.f};

    for (int g = 0; g < CHUNK / 8; ++g) {
        __syncthreads();
        // stage 8 tokens x 64 dims of k and v, coalesced
        #pragma unroll
        for (int j = 0; j < 2; ++j) {
            int e = j * 256 + t;
            int tok = e >> 6, d = e & 63;
            size_t off = (size_t)(g * 8 + tok) * Esz + d;
            ksh[e] = kb[off];
            vsh[e] = vb[off];
        }
        if (t < 8) {
            int l = l0 + g * 8 + t;
            float ang = 1.5707963267948966f * (float)(l + 1) / (float)Lsz;
            float m = mb[g * 8 + t];
            ssh[t] = sinf(ang) * m;   // fold one mask factor into s/c
            csh[t] = cosf(ang) * m;
            msh[t] = m;               // second mask factor applied to v
        }
        __syncthreads();

        #pragma unroll
        for (int tok = 0; tok < 8; ++tok) {
            float s = ssh[tok], c = csh[tok], m = msh[tok];
            float4 k4 = *(const float4*)&ksh[tok * 64 + dg * 4];
            float4 v4 = *(const float4*)&vsh[tok * 64 + mg * 4];
            float rk[4] = { fmaxf(k4.x, 0.f), fmaxf(k4.y, 0.f),
                            fmaxf(k4.z, 0.f), fmaxf(k4.w, 0.f) };
            float vm[4] = { v4.x * m, v4.y * m, v4.z * m, v4.w * m };
            float sk[4], ck[4];
            #pragma unroll
            for (int i = 0; i < 4; ++i) { sk[i] = s * rk[i]; ck[i] = c * rk[i]; }
            if (mg == 0) {
                #pragma unroll
                for (int i = 0; i < 4; ++i) { aks[i] += sk[i]; akc[i] += ck[i]; }
            }
            #pragma unroll
            for (int i = 0; i < 4; ++i)
                #pragma unroll
                for (int j = 0; j < 4; ++j) {
                    aA[i][j] += sk[i] * vm[j];
                    aB[i][j] += ck[i] * vm[j];
                }
        }
    }

    float* p = g_part + (size_t)(n * SPLIT + sp) * PART;
    #pragma unroll
    for (int i = 0; i < 4; ++i) {
        int d = dg * 4 + i;
        *(float4*)&p[OFF_A + d * 64 + mg * 4] =
            make_float4(aA[i][0], aA[i][1], aA[i][2], aA[i][3]);
        *(float4*)&p[OFF_B + d * 64 + mg * 4] =
            make_float4(aB[i][0], aB[i][1], aB[i][2], aB[i][3]);
    }
    if (mg == 0) {
        #pragma unroll
        for (int i = 0; i < 4; ++i) {
            p[OFF_KS + dg * 4 + i] = aks[i];
            p[OFF_KC + dg * 4 + i] = akc[i];
        }
    }
}

// ---------------------------------------------------------------------------
// Reduce the SPLIT partials per head (deterministic, fixed order)
// ---------------------------------------------------------------------------
__global__ __launch_bounds__(256) void k_reduce() {
    int n = blockIdx.x;
    for (int i = threadIdx.x; i < PART; i += 256) {
        float s = 0.f;
        #pragma unroll
        for (int sp = 0; sp < SPLIT; ++sp)
            s += g_part[(size_t)(n * SPLIT + sp) * PART + i];
        g_kv[(size_t)n * PART + i] = s;
    }
}

// ---------------------------------------------------------------------------
// Phase 2: out[l][m] = z_l * ( s_l * rq[l]@A + c_l * rq[l]@B )[m]
//          z_l = 1 / max( s_l * rq@ks + c_l * rq@kc, eps )
// dynamic smem layout (floats):
//   Ash[4096] | Bsh[4096] | rq[64*68] | ks[64] | kc[64] | z[64] | s[64] | c[64]
// ---------------------------------------------------------------------------
#define RQ_ST 68
#define SM2_FLOATS (4096 + 4096 + 64 * RQ_ST + 64 * 5)
#define SM2_BYTES  (SM2_FLOATS * 4)

__global__ __launch_bounds__(256) void k_phase2(const float* __restrict__ Q,
                                                float* __restrict__ O) {
    extern __shared__ float sm2[];
    float* Ash  = sm2;
    float* Bsh  = sm2 + 4096;
    float* rq   = sm2 + 8192;
    float* kssh = sm2 + 8192 + 64 * RQ_ST;
    float* kcsh = kssh + 64;
    float* zsh  = kcsh + 64;
    float* ssh  = zsh + 64;
    float* csh  = ssh + 64;

    int blk = blockIdx.x;
    int n = blk >> 6;          // head
    int tile = blk & 63;       // 64-token tile
    int b = n >> 4, h = n & 15;
    int l0 = tile * 64;

    const float* qb = Q + ((size_t)b * Lsz + l0) * Esz + h * Dsz;
    const float* kv = g_kv + (size_t)n * PART;
    int t = threadIdx.x;

    for (int i = t; i < 4096; i += 256) {
        Ash[i] = kv[OFF_A + i];
        Bsh[i] = kv[OFF_B + i];
    }
    if (t < 64) {
        kssh[t] = kv[OFF_KS + t];
        kcsh[t] = kv[OFF_KC + t];
        int l = l0 + t;
        float ang = 1.5707963267948966f * (float)(l + 1) / (float)Lsz;
        ssh[t] = sinf(ang);
        csh[t] = cosf(ang);
    }
    // stage relu(q), transposed: rq[d][tok]
    #pragma unroll
    for (int j = 0; j < 16; ++j) {
        int e = j * 256 + t;
        int tok = e >> 6, d = e & 63;
        rq[d * RQ_ST + tok] = fmaxf(qb[(size_t)tok * Esz + d], 0.f);
    }
    __syncthreads();

    // normalizer per token
    if (t < 64) {
        float s = ssh[t], c = csh[t], acc = 0.f;
        #pragma unroll 8
        for (int d = 0; d < 64; ++d)
            acc += rq[d * RQ_ST + t] * (s * kssh[d] + c * kcsh[d]);
        zsh[t] = 1.f / fmaxf(acc, 1e-6f);
    }
    __syncthreads();

    int tg = t >> 4;           // token group: tokens tg*4..tg*4+3
    int mg = t & 15;           // m group:     m mg*4..mg*4+3
    float sv[4], cv[4];
    #pragma unroll
    for (int i = 0; i < 4; ++i) { sv[i] = ssh[tg * 4 + i]; cv[i] = csh[tg * 4 + i]; }

    float acc[4][4] = {{0.f}};
    #pragma unroll 4
    for (int d = 0; d < 64; ++d) {
        float4 q4 = *(const float4*)&rq[d * RQ_ST + tg * 4];
        float4 a4 = *(const float4*)&Ash[d * 64 + mg * 4];
        float4 b4 = *(const float4*)&Bsh[d * 64 + mg * 4];
        float qq[4] = { q4.x, q4.y, q4.z, q4.w };
        float aa[4] = { a4.x, a4.y, a4.z, a4.w };
        float bb[4] = { b4.x, b4.y, b4.z, b4.w };
        #pragma unroll
        for (int i = 0; i < 4; ++i) {
            float u = qq[i] * sv[i];
            float w = qq[i] * cv[i];
            #pragma unroll
            for (int j = 0; j < 4; ++j)
                acc[i][j] += u * aa[j] + w * bb[j];
        }
    }

    float* ob = O + ((size_t)n * Lsz + l0) * Dsz;
    #pragma unroll
    for (int i = 0; i < 4; ++i) {
        int tok = tg * 4 + i;
        float z = zsh[tok];
        *(float4*)&ob[(size_t)tok * Dsz + mg * 4] =
            make_float4(acc[i][0] * z, acc[i][1] * z, acc[i][2] * z, acc[i][3] * z);
    }
}

// ---------------------------------------------------------------------------
extern "C" void kernel_launch(void* const* d_in, const int* in_sizes, int n_in,
                              void* d_out, int out_size) {
    const float* q = (const float*)d_in[0];
    const float* k = (const float*)d_in[1];
    const float* v = (const float*)d_in[2];
    const float* m = (const float*)d_in[3];
    float* out = (float*)d_out;

    cudaFuncSetAttribute(k_phase2, cudaFuncAttributeMaxDynamicSharedMemorySize,
                         SM2_BYTES);

    k_phase1<<<HEADS * SPLIT, 256>>>(k, v, m);
    k_reduce<<<HEADS, 256>>>();
    k_phase2<<<HEADS * 64, 256, SM2_BYTES>>>(q, out);
}

// round 2
// speedup vs baseline: 1.5148x; 1.5148x over previous
#include <cuda_runtime.h>
#include <math.h>

#define Bsz   4
#define Lsz   4096
#define Esz   1024
#define Hsz   16
#define Dsz   64
#define HEADS 64
#define SPLIT 16
#define CHUNK 256            // Lsz / SPLIT
#define GT    16             // tokens staged per group (phase 1)

#define PART   8320          // A(4096) + B(4096) + ks(64) + kc(64)
#define OFF_A  0
#define OFF_B  4096
#define OFF_KS 8192
#define OFF_KC 8256

// Scratch (no allocations allowed in kernel_launch)
__device__ float g_part[HEADS * SPLIT * PART];   // ~34 MB
__device__ float g_kv[HEADS * PART];             // ~2.1 MB

// ---------------------------------------------------------------------------
// Phase 1: per (head, L-split) partial accumulation.
//   threads 0..63  : A[d][m] += s_l*relu(k)[d] * (m_l^2 folded) * v[m], 8x8 tile
//   threads 64..127: B[d][m] with cos
// All relu/sin/cos/mask math folded into the staging step (done once).
// ---------------------------------------------------------------------------
__global__ __launch_bounds__(128) void k_phase1(const float* __restrict__ K,
                                                const float* __restrict__ V,
                                                const float* __restrict__ M) {
    int blk = blockIdx.x;
    int n  = blk >> 4;         // head (0..63)
    int sp = blk & 15;         // L split (0..15)
    int b = n >> 4, h = n & 15;
    int l0 = sp * CHUNK;

    const float* kb = K + ((size_t)b * Lsz + l0) * Esz + h * Dsz;
    const float* vb = V + ((size_t)b * Lsz + l0) * Esz + h * Dsz;
    const float* mb = M + (size_t)b * Lsz + l0;

    __shared__ float ssh[CHUNK], csh[CHUNK], msh[CHUNK];
    __shared__ float skh[GT * 64];   // s_l * mask * relu(k)
    __shared__ float ckh[GT * 64];   // c_l * mask * relu(k)
    __shared__ float vmh[GT * 64];   // mask * v

    int t = threadIdx.x;

    // precompute per-token sin/cos (mask folded) for the whole chunk
    for (int i = t; i < CHUNK; i += 128) {
        int l = l0 + i;
        float ang = 1.5707963267948966f * (float)(l + 1) / (float)Lsz;
        float m = mb[i];
        ssh[i] = sinf(ang) * m;
        csh[i] = cosf(ang) * m;
        msh[i] = m;
    }

    bool isA = (t < 64);
    int tt = t & 63;
    int dg = tt >> 3;          // d block: d = dg*8 .. dg*8+7
    int mg = tt & 7;           // m block: m = mg*8 .. mg*8+7
    const float* xsh = isA ? skh : ckh;

    float acc[8][8];
    #pragma unroll
    for (int i = 0; i < 8; ++i)
        #pragma unroll
        for (int j = 0; j < 8; ++j) acc[i][j] = 0.f;
    float aks = 0.f;           // ks[tt] for A-threads, kc[tt] for B-threads

    for (int g = 0; g < CHUNK / GT; ++g) {
        __syncthreads();
        // stage GT tokens x 64 dims: 256 float4 across 128 threads
        #pragma unroll
        for (int j = 0; j < 2; ++j) {
            int e4 = j * 128 + t;          // float4 index
            int tok = e4 >> 4;             // 16 float4 per token
            int dd = (e4 & 15) * 4;
            int li = g * GT + tok;
            float4 k4 = *(const float4*)&kb[(size_t)li * Esz + dd];
            float4 v4 = *(const float4*)&vb[(size_t)li * Esz + dd];
            float s = ssh[li], c = csh[li], m = msh[li];
            float rx = fmaxf(k4.x, 0.f), ry = fmaxf(k4.y, 0.f);
            float rz = fmaxf(k4.z, 0.f), rw = fmaxf(k4.w, 0.f);
            *(float4*)&skh[tok * 64 + dd] = make_float4(rx * s, ry * s, rz * s, rw * s);
            *(float4*)&ckh[tok * 64 + dd] = make_float4(rx * c, ry * c, rz * c, rw * c);
            *(float4*)&vmh[tok * 64 + dd] = make_float4(v4.x * m, v4.y * m, v4.z * m, v4.w * m);
        }
        __syncthreads();

        // ks/kc column sums (each thread owns one d = tt)
        #pragma unroll
        for (int tok = 0; tok < GT; ++tok) aks += xsh[tok * 64 + tt];

        // 8x8 outer-product accumulation
        #pragma unroll
        for (int tok = 0; tok < GT; ++tok) {
            float x[8], y[8];
            float4 x0 = *(const float4*)&xsh[tok * 64 + dg * 8];
            float4 x1 = *(const float4*)&xsh[tok * 64 + dg * 8 + 4];
            float4 y0 = *(const float4*)&vmh[tok * 64 + mg * 8];
            float4 y1 = *(const float4*)&vmh[tok * 64 + mg * 8 + 4];
            x[0]=x0.x; x[1]=x0.y; x[2]=x0.z; x[3]=x0.w;
            x[4]=x1.x; x[5]=x1.y; x[6]=x1.z; x[7]=x1.w;
            y[0]=y0.x; y[1]=y0.y; y[2]=y0.z; y[3]=y0.w;
            y[4]=y1.x; y[5]=y1.y; y[6]=y1.z; y[7]=y1.w;
            #pragma unroll
            for (int i = 0; i < 8; ++i)
                #pragma unroll
                for (int j = 0; j < 8; ++j)
                    acc[i][j] += x[i] * y[j];
        }
    }

    float* p = g_part + (size_t)blk * PART;
    int off = isA ? OFF_A : OFF_B;
    #pragma unroll
    for (int i = 0; i < 8; ++i) {
        int d = dg * 8 + i;
        *(float4*)&p[off + d * 64 + mg * 8] =
            make_float4(acc[i][0], acc[i][1], acc[i][2], acc[i][3]);
        *(float4*)&p[off + d * 64 + mg * 8 + 4] =
            make_float4(acc[i][4], acc[i][5], acc[i][6], acc[i][7]);
    }
    p[(isA ? OFF_KS : OFF_KC) + tt] = aks;
}

// ---------------------------------------------------------------------------
// Reduce the SPLIT partials per head (deterministic, fixed order)
// ---------------------------------------------------------------------------
__global__ __launch_bounds__(256) void k_reduce() {
    int n = blockIdx.x;
    for (int i = threadIdx.x; i < PART; i += 256) {
        float s = 0.f;
        #pragma unroll
        for (int sp = 0; sp < SPLIT; ++sp)
            s += g_part[(size_t)(n * SPLIT + sp) * PART + i];
        g_kv[(size_t)n * PART + i] = s;
    }
}

// ---------------------------------------------------------------------------
// Phase 2: out[l][m] = z_l * ( s_l * rq[l]@A + c_l * rq[l]@B )[m]
// Tile: 128 tokens x 64 m per block, thread tile 8 tok x 8 m, sin/cos folded
// from registers in the inner loop (1.5 FMA per byte loaded).
// dynamic smem (floats):
//   A[4096] | B[4096] | rq[128*65] | ss[128] | cs[128] | zs[128] | ks[64] | kc[64]
// ---------------------------------------------------------------------------
#define TT    128
#define RQS   65
#define SM2_FLOATS (4096 + 4096 + TT * RQS + 3 * TT + 128)
#define SM2_BYTES  (SM2_FLOATS * 4)

__global__ __launch_bounds__(128) void k_phase2(const float* __restrict__ Q,
                                                float* __restrict__ O) {
    extern __shared__ float sm2[];
    float* Ash  = sm2;
    float* Bsh  = sm2 + 4096;
    float* rqsh = sm2 + 8192;
    float* ssh  = rqsh + TT * RQS;
    float* csh  = ssh + TT;
    float* zsh  = csh + TT;
    float* ks2  = zsh + TT;
    float* kc2  = ks2 + 64;

    int blk = blockIdx.x;
    int n = blk >> 5;          // head
    int tile = blk & 31;       // 128-token tile
    int b = n >> 4, h = n & 15;
    int l0 = tile * TT;

    const float* qb = Q + ((size_t)b * Lsz + l0) * Esz + h * Dsz;
    const float* kv = g_kv + (size_t)n * PART;
    int t = threadIdx.x;

    // stage A, B (8192 floats, float4)
    #pragma unroll
    for (int j = 0; j < 8; ++j) {
        int e4 = j * 128 + t;
        *(float4*)&Ash[e4 * 4] = *(const float4*)&kv[OFF_A + e4 * 4];
        *(float4*)&Bsh[e4 * 4] = *(const float4*)&kv[OFF_B + e4 * 4];
    }
    if (t < 64) {
        ks2[t] = kv[OFF_KS + t];
        kc2[t] = kv[OFF_KC + t];
    }
    {
        int l = l0 + t;
        float ang = 1.5707963267948966f * (float)(l + 1) / (float)Lsz;
        ssh[t] = sinf(ang);
        csh[t] = cosf(ang);
    }
    // stage relu(q): [tok][d], row stride 65 (odd -> conflict-free columns)
    #pragma unroll
    for (int j = 0; j < 16; ++j) {
        int e4 = j * 128 + t;
        int tok = e4 >> 4;
        int dd = (e4 & 15) * 4;
        float4 q4 = *(const float4*)&qb[(size_t)tok * Esz + dd];
        float* r = &rqsh[tok * RQS + dd];
        r[0] = fmaxf(q4.x, 0.f);
        r[1] = fmaxf(q4.y, 0.f);
        r[2] = fmaxf(q4.z, 0.f);
        r[3] = fmaxf(q4.w, 0.f);
    }
    __syncthreads();

    // normalizer: one token per thread
    {
        float s = ssh[t], c = csh[t], a = 0.f;
        const float* r = &rqsh[t * RQS];
        #pragma unroll 8
        for (int d = 0; d < 64; ++d)
            a += r[d] * (s * ks2[d] + c * kc2[d]);
        zsh[t] = 1.f / fmaxf(a, 1e-6f);
    }
    __syncthreads();

    int tg = t >> 3;           // token group (0..15): tokens tg*8..tg*8+7
    int mg = t & 7;            // m group: m = mg*8..mg*8+7
    int m0 = mg * 8;
    float sv[8], cv[8];
    #pragma unroll
    for (int i = 0; i < 8; ++i) { sv[i] = ssh[tg * 8 + i]; cv[i] = csh[tg * 8 + i]; }

    float acc[8][8];
    #pragma unroll
    for (int i = 0; i < 8; ++i)
        #pragma unroll
        for (int j = 0; j < 8; ++j) acc[i][j] = 0.f;

    #pragma unroll 8
    for (int d = 0; d < 64; ++d) {
        float rv[8];
        #pragma unroll
        for (int i = 0; i < 8; ++i) rv[i] = rqsh[(tg * 8 + i) * RQS + d];
        float4 a0 = *(const float4*)&Ash[d * 64 + m0];
        float4 a1 = *(const float4*)&Ash[d * 64 + m0 + 4];
        float4 b0 = *(const float4*)&Bsh[d * 64 + m0];
        float4 b1 = *(const float4*)&Bsh[d * 64 + m0 + 4];
        float aa[8] = { a0.x, a0.y, a0.z, a0.w, a1.x, a1.y, a1.z, a1.w };
        float bb[8] = { b0.x, b0.y, b0.z, b0.w, b1.x, b1.y, b1.z, b1.w };
        #pragma unroll
        for (int i = 0; i < 8; ++i) {
            float u = sv[i] * rv[i];
            float w = cv[i] * rv[i];
            #pragma unroll
            for (int j = 0; j < 8; ++j)
                acc[i][j] += u * aa[j] + w * bb[j];
        }
    }

    float* ob = O + ((size_t)n * Lsz + l0) * Dsz;
    #pragma unroll
    for (int i = 0; i < 8; ++i) {
        int tok = tg * 8 + i;
        float z = zsh[tok];
        *(float4*)&ob[(size_t)tok * Dsz + m0] =
            make_float4(acc[i][0] * z, acc[i][1] * z, acc[i][2] * z, acc[i][3] * z);
        *(float4*)&ob[(size_t)tok * Dsz + m0 + 4] =
            make_float4(acc[i][4] * z, acc[i][5] * z, acc[i][6] * z, acc[i][7] * z);
    }
}

// ---------------------------------------------------------------------------
extern "C" void kernel_launch(void* const* d_in, const int* in_sizes, int n_in,
                              void* d_out, int out_size) {
    const float* q = (const float*)d_in[0];
    const float* k = (const float*)d_in[1];
    const float* v = (const float*)d_in[2];
    const float* m = (const float*)d_in[3];
    float* out = (float*)d_out;

    cudaFuncSetAttribute(k_phase2, cudaFuncAttributeMaxDynamicSharedMemorySize,
                         SM2_BYTES);

    k_phase1<<<HEADS * SPLIT, 128>>>(k, v, m);
    k_reduce<<<HEADS, 256>>>();
    k_phase2<<<HEADS * 32, 128, SM2_BYTES>>>(q, out);
}